// round 1
// baseline (speedup 1.0000x reference)
#include <cuda_runtime.h>
#include <cuda_bf16.h>

// Problem constants
#define NTOK 8192        // B*S = 4*2048
#define DDIM 1024
#define NEXP 8
#define EPSV 1e-4f
#define WTHR 0.1f

// Scratch (device globals: no allocation allowed)
__device__ int   g_cnt[NEXP];
__device__ int   g_tok[NEXP][NTOK];
__device__ float g_wt [NEXP][NTOK];
__device__ int   g_eid[NTOK * 2];
__device__ float g_w  [NTOK * 2];

// ---------------------------------------------------------------------------
// Zero per-expert counters (must run every launch; graph replays it too)
// ---------------------------------------------------------------------------
__global__ void zero_counts_kernel() {
    if (threadIdx.x < NEXP) g_cnt[threadIdx.x] = 0;
}

// ---------------------------------------------------------------------------
// Gating: one warp per token.
//   scores = max(x @ gW + gb, EPS); p = softmax(scores)
//   top-2 (JAX tie-break: lowest index wins) ; w = max(p,0.1)/total/K
// Appends (token, weight) into per-expert buckets.
// ---------------------------------------------------------------------------
__global__ void gating_kernel(const float* __restrict__ x,
                              const float* __restrict__ gW,
                              const float* __restrict__ gb)
{
    const int warp = (blockIdx.x * blockDim.x + threadIdx.x) >> 5;
    const int lane = threadIdx.x & 31;
    if (warp >= NTOK) return;

    const float* xr = x + (size_t)warp * DDIM;

    float acc[NEXP];
#pragma unroll
    for (int e = 0; e < NEXP; e++) acc[e] = 0.0f;

    // gate_W is [D, E] row-major with E=8 -> each row is 2 float4
    const float4* gW4 = reinterpret_cast<const float4*>(gW);
#pragma unroll 4
    for (int d = lane; d < DDIM; d += 32) {
        const float xv = __ldg(xr + d);
        const float4 ga = __ldg(gW4 + d * 2 + 0);
        const float4 gbv = __ldg(gW4 + d * 2 + 1);
        acc[0] = fmaf(xv, ga.x,  acc[0]);
        acc[1] = fmaf(xv, ga.y,  acc[1]);
        acc[2] = fmaf(xv, ga.z,  acc[2]);
        acc[3] = fmaf(xv, ga.w,  acc[3]);
        acc[4] = fmaf(xv, gbv.x, acc[4]);
        acc[5] = fmaf(xv, gbv.y, acc[5]);
        acc[6] = fmaf(xv, gbv.z, acc[6]);
        acc[7] = fmaf(xv, gbv.w, acc[7]);
    }

#pragma unroll
    for (int e = 0; e < NEXP; e++) {
#pragma unroll
        for (int off = 16; off > 0; off >>= 1)
            acc[e] += __shfl_xor_sync(0xffffffffu, acc[e], off);
    }

    if (lane == 0) {
        float s[NEXP], p[NEXP];
        float mx = -1e30f;
#pragma unroll
        for (int e = 0; e < NEXP; e++) {
            s[e] = fmaxf(acc[e] + gb[e], EPSV);   // TEMP = 1.0
            mx = fmaxf(mx, s[e]);
        }
        float Z = 0.0f;
#pragma unroll
        for (int e = 0; e < NEXP; e++) { p[e] = expf(s[e] - mx); Z += p[e]; }
        const float invZ = 1.0f / Z;
#pragma unroll
        for (int e = 0; e < NEXP; e++) p[e] *= invZ;

        // top-2 with strict '>' => lowest index wins on ties (JAX semantics)
        int i0 = 0;
#pragma unroll
        for (int e = 1; e < NEXP; e++) if (p[e] > p[i0]) i0 = e;
        int i1 = -1;
        float best = -1e30f;
#pragma unroll
        for (int e = 0; e < NEXP; e++) {
            if (e != i0 && p[e] > best) { best = p[e]; i1 = e; }
        }

        float w0 = fmaxf(p[i0], WTHR);
        float w1 = fmaxf(p[i1], WTHR);
        const float scale = 0.5f / (w0 + w1);     // includes the /K (K=2)
        w0 *= scale;
        w1 *= scale;

        g_eid[2 * warp + 0] = i0;  g_w[2 * warp + 0] = w0;
        g_eid[2 * warp + 1] = i1;  g_w[2 * warp + 1] = w1;

        int s0 = atomicAdd(&g_cnt[i0], 1);
        g_tok[i0][s0] = warp;  g_wt[i0][s0] = w0;
        int s1 = atomicAdd(&g_cnt[i1], 1);
        g_tok[i1][s1] = warp;  g_wt[i1][s1] = w1;
    }
}

// ---------------------------------------------------------------------------
// Bias epilogue init: out[t,f] = w0*b[e0,f] + w1*b[e1,f]
// (also initializes every output element; GEMM atomically adds on top)
// ---------------------------------------------------------------------------
__global__ void bias_init_kernel(const float* __restrict__ eb,
                                 float* __restrict__ out)
{
    const int idx = blockIdx.x * blockDim.x + threadIdx.x;
    if (idx >= NTOK * DDIM) return;
    const int t = idx >> 10;           // /DDIM
    const int f = idx & (DDIM - 1);
    const int e0 = g_eid[2 * t + 0];
    const int e1 = g_eid[2 * t + 1];
    out[idx] = g_w[2 * t + 0] * __ldg(eb + e0 * DDIM + f)
             + g_w[2 * t + 1] * __ldg(eb + e1 * DDIM + f);
}

// ---------------------------------------------------------------------------
// Grouped GEMM: for expert e, C = gather(X, bucket_e) @ W_e, rows scaled by
// routing weight, atomically accumulated into out.
// Tiles: BM=64 tokens x BN=64 cols x BK=32, 256 threads, 4x4 microtile.
// ---------------------------------------------------------------------------
#define BM 64
#define BN 64
#define BK 32

__global__ __launch_bounds__(256, 2)
void expert_gemm_kernel(const float* __restrict__ x,
                        const float* __restrict__ eW,
                        float* __restrict__ out)
{
    const int e    = blockIdx.z;
    const int n    = g_cnt[e];
    const int row0 = blockIdx.y * BM;
    if (row0 >= n) return;
    const int col0 = blockIdx.x * BN;

    __shared__ float As[BK][BM + 4];   // transposed A tile (k-major)
    __shared__ float Bs[BK][BN];
    __shared__ int   stok[BM];
    __shared__ float swt[BM];

    const int tid = threadIdx.x;

    if (tid < BM) {
        const int r = row0 + tid;
        if (r < n) { stok[tid] = g_tok[e][r]; swt[tid] = g_wt[e][r]; }
        else       { stok[tid] = -1;          swt[tid] = 0.0f; }
    }
    __syncthreads();

    // A-load mapping: 64 rows x 8 float4 in k; 4 threads/row, 2 float4 each
    const int ar   = tid >> 2;          // 0..63
    const int ac4  = tid & 3;           // float4 group: ac4 and ac4+4
    const int atok = stok[ar];
    const float* xrow = x + (size_t)(atok < 0 ? 0 : atok) * DDIM;

    // B-load mapping: 32 k-rows x 16 float4; 8 threads/row, 2 float4 each
    const int br  = tid >> 3;           // 0..31
    const int bc4 = tid & 7;            // float4 group: bc4 and bc4+8
    const float* We = eW + (size_t)e * DDIM * DDIM;

    const int ty = tid >> 4;            // 0..15
    const int tx = tid & 15;            // 0..15

    float c[4][4];
#pragma unroll
    for (int i = 0; i < 4; i++)
#pragma unroll
        for (int j = 0; j < 4; j++) c[i][j] = 0.0f;

    for (int k0 = 0; k0 < DDIM; k0 += BK) {
        // global loads (issued before the sync to overlap with prior compute)
        float4 a0 = make_float4(0.f, 0.f, 0.f, 0.f), a1 = a0;
        if (atok >= 0) {
            a0 = *reinterpret_cast<const float4*>(xrow + k0 + ac4 * 4);
            a1 = *reinterpret_cast<const float4*>(xrow + k0 + (ac4 + 4) * 4);
        }
        const float4 b0 = *reinterpret_cast<const float4*>(
            We + (size_t)(k0 + br) * DDIM + col0 + bc4 * 4);
        const float4 b1 = *reinterpret_cast<const float4*>(
            We + (size_t)(k0 + br) * DDIM + col0 + (bc4 + 8) * 4);

        __syncthreads();   // previous tile fully consumed

        // store A transposed: As[k][row]
        {
            const int kb = ac4 * 4;
            As[kb + 0][ar] = a0.x; As[kb + 1][ar] = a0.y;
            As[kb + 2][ar] = a0.z; As[kb + 3][ar] = a0.w;
            const int kb2 = (ac4 + 4) * 4;
            As[kb2 + 0][ar] = a1.x; As[kb2 + 1][ar] = a1.y;
            As[kb2 + 2][ar] = a1.z; As[kb2 + 3][ar] = a1.w;
        }
        *reinterpret_cast<float4*>(&Bs[br][bc4 * 4])       = b0;
        *reinterpret_cast<float4*>(&Bs[br][(bc4 + 8) * 4]) = b1;

        __syncthreads();

#pragma unroll
        for (int kk = 0; kk < BK; kk++) {
            const float4 av = *reinterpret_cast<const float4*>(&As[kk][ty * 4]);
            const float4 bv = *reinterpret_cast<const float4*>(&Bs[kk][tx * 4]);
            const float a[4] = {av.x, av.y, av.z, av.w};
            const float b[4] = {bv.x, bv.y, bv.z, bv.w};
#pragma unroll
            for (int i = 0; i < 4; i++)
#pragma unroll
                for (int j = 0; j < 4; j++)
                    c[i][j] = fmaf(a[i], b[j], c[i][j]);
        }
    }

    // epilogue: scale by routing weight, atomic-accumulate into out
#pragma unroll
    for (int i = 0; i < 4; i++) {
        const int r   = ty * 4 + i;
        const int tok = stok[r];
        if (tok < 0) continue;
        const float w = swt[r];
        float* o = out + (size_t)tok * DDIM + col0 + tx * 4;
        atomicAdd(o + 0, w * c[i][0]);
        atomicAdd(o + 1, w * c[i][1]);
        atomicAdd(o + 2, w * c[i][2]);
        atomicAdd(o + 3, w * c[i][3]);
    }
}

// ---------------------------------------------------------------------------
extern "C" void kernel_launch(void* const* d_in, const int* in_sizes, int n_in,
                              void* d_out, int out_size)
{
    const float* x  = (const float*)d_in[0];   // [4,2048,1024]
    const float* gW = (const float*)d_in[1];   // [1024,8]
    const float* gb = (const float*)d_in[2];   // [8]
    const float* eW = (const float*)d_in[3];   // [8,1024,1024]
    const float* eb = (const float*)d_in[4];   // [8,1024]
    float* out = (float*)d_out;                // [4,2048,1024]

    zero_counts_kernel<<<1, 32>>>();
    gating_kernel<<<NTOK / 8, 256>>>(x, gW, gb);          // 8 warps/block
    bias_init_kernel<<<(NTOK * DDIM) / 256, 256>>>(eb, out);
    dim3 grid(DDIM / BN, NTOK / BM, NEXP);                // (16,128,8), most y-tiles exit early
    expert_gemm_kernel<<<grid, 256>>>(x, eW, out);
}

// round 2
// speedup vs baseline: 2.8662x; 2.8662x over previous
#include <cuda_runtime.h>
#include <cuda_bf16.h>
#include <cstdint>

// Problem constants
#define NTOK 8192        // B*S = 4*2048
#define DDIM 1024
#define NEXP 8
#define EPSV 1e-4f
#define WTHR 0.1f

// Scratch (device globals: no allocation allowed)
__device__ int   g_cnt[NEXP];
__device__ int   g_tok[NEXP][NTOK];
__device__ float g_wt [NEXP][NTOK];
__device__ int   g_eid[NTOK * 2];
__device__ float g_w  [NTOK * 2];

// ---------------------------------------------------------------------------
__global__ void zero_counts_kernel() {
    if (threadIdx.x < NEXP) g_cnt[threadIdx.x] = 0;
}

// ---------------------------------------------------------------------------
// Gating: one warp per token (unchanged from round 1 — passed exactly).
// ---------------------------------------------------------------------------
__global__ void gating_kernel(const float* __restrict__ x,
                              const float* __restrict__ gW,
                              const float* __restrict__ gb)
{
    const int warp = (blockIdx.x * blockDim.x + threadIdx.x) >> 5;
    const int lane = threadIdx.x & 31;
    if (warp >= NTOK) return;

    const float* xr = x + (size_t)warp * DDIM;

    float acc[NEXP];
#pragma unroll
    for (int e = 0; e < NEXP; e++) acc[e] = 0.0f;

    const float4* gW4 = reinterpret_cast<const float4*>(gW);
#pragma unroll 4
    for (int d = lane; d < DDIM; d += 32) {
        const float xv = __ldg(xr + d);
        const float4 ga = __ldg(gW4 + d * 2 + 0);
        const float4 gbv = __ldg(gW4 + d * 2 + 1);
        acc[0] = fmaf(xv, ga.x,  acc[0]);
        acc[1] = fmaf(xv, ga.y,  acc[1]);
        acc[2] = fmaf(xv, ga.z,  acc[2]);
        acc[3] = fmaf(xv, ga.w,  acc[3]);
        acc[4] = fmaf(xv, gbv.x, acc[4]);
        acc[5] = fmaf(xv, gbv.y, acc[5]);
        acc[6] = fmaf(xv, gbv.z, acc[6]);
        acc[7] = fmaf(xv, gbv.w, acc[7]);
    }

#pragma unroll
    for (int e = 0; e < NEXP; e++) {
#pragma unroll
        for (int off = 16; off > 0; off >>= 1)
            acc[e] += __shfl_xor_sync(0xffffffffu, acc[e], off);
    }

    if (lane == 0) {
        float s[NEXP], p[NEXP];
        float mx = -1e30f;
#pragma unroll
        for (int e = 0; e < NEXP; e++) {
            s[e] = fmaxf(acc[e] + gb[e], EPSV);
            mx = fmaxf(mx, s[e]);
        }
        float Z = 0.0f;
#pragma unroll
        for (int e = 0; e < NEXP; e++) { p[e] = expf(s[e] - mx); Z += p[e]; }
        const float invZ = 1.0f / Z;
#pragma unroll
        for (int e = 0; e < NEXP; e++) p[e] *= invZ;

        int i0 = 0;
#pragma unroll
        for (int e = 1; e < NEXP; e++) if (p[e] > p[i0]) i0 = e;
        int i1 = -1;
        float best = -1e30f;
#pragma unroll
        for (int e = 0; e < NEXP; e++) {
            if (e != i0 && p[e] > best) { best = p[e]; i1 = e; }
        }

        float w0 = fmaxf(p[i0], WTHR);
        float w1 = fmaxf(p[i1], WTHR);
        const float scale = 0.5f / (w0 + w1);
        w0 *= scale;
        w1 *= scale;

        g_eid[2 * warp + 0] = i0;  g_w[2 * warp + 0] = w0;
        g_eid[2 * warp + 1] = i1;  g_w[2 * warp + 1] = w1;

        int s0 = atomicAdd(&g_cnt[i0], 1);
        g_tok[i0][s0] = warp;  g_wt[i0][s0] = w0;
        int s1 = atomicAdd(&g_cnt[i1], 1);
        g_tok[i1][s1] = warp;  g_wt[i1][s1] = w1;
    }
}

// ---------------------------------------------------------------------------
// Bias init: out[t,f] = w0*b[e0,f] + w1*b[e1,f]   (covers the 0xAA poison)
// ---------------------------------------------------------------------------
__global__ void bias_init_kernel(const float* __restrict__ eb,
                                 float* __restrict__ out)
{
    const int idx = blockIdx.x * blockDim.x + threadIdx.x;
    if (idx >= NTOK * DDIM) return;
    const int t = idx >> 10;
    const int f = idx & (DDIM - 1);
    const int e0 = g_eid[2 * t + 0];
    const int e1 = g_eid[2 * t + 1];
    out[idx] = g_w[2 * t + 0] * __ldg(eb + e0 * DDIM + f)
             + g_w[2 * t + 1] * __ldg(eb + e1 * DDIM + f);
}

// ---------------------------------------------------------------------------
// tf32 tensor-core grouped GEMM.
// CTA tile 128x128x32, 8 warps (2 M x 4 N), warp tile 64x32 via m16n8k8.
// ---------------------------------------------------------------------------
#define BM 128
#define BN 128
#define BK 32
#define AS_STRIDE 36    // bank = 4*m + k  -> conflict-free frag loads
#define BS_STRIDE 136   // bank = 8*k + n  -> conflict-free frag loads

__device__ __forceinline__ uint32_t f2tf32(float f) {
    uint32_t r;
    asm("cvt.rna.tf32.f32 %0, %1;" : "=r"(r) : "f"(f));
    return r;
}

__device__ __forceinline__ void mma_tf32(float& d0, float& d1, float& d2, float& d3,
                                         uint32_t a0, uint32_t a1, uint32_t a2, uint32_t a3,
                                         uint32_t b0, uint32_t b1)
{
    asm volatile(
        "mma.sync.aligned.m16n8k8.row.col.f32.tf32.tf32.f32 "
        "{%0,%1,%2,%3}, {%4,%5,%6,%7}, {%8,%9}, {%0,%1,%2,%3};"
        : "+f"(d0), "+f"(d1), "+f"(d2), "+f"(d3)
        : "r"(a0), "r"(a1), "r"(a2), "r"(a3), "r"(b0), "r"(b1));
}

__global__ __launch_bounds__(256, 2)
void expert_gemm_kernel(const float* __restrict__ x,
                        const float* __restrict__ eW,
                        float* __restrict__ out)
{
    const int e    = blockIdx.z;
    const int n    = g_cnt[e];
    const int row0 = blockIdx.y * BM;
    if (row0 >= n) return;
    const int col0 = blockIdx.x * BN;

    __shared__ uint32_t As[BM][AS_STRIDE];
    __shared__ uint32_t Bs[BK][BS_STRIDE];
    __shared__ int      stok[BM];
    __shared__ float    swt[BM];

    const int tid  = threadIdx.x;
    const int lane = tid & 31;
    const int wid  = tid >> 5;
    const int wm   = wid & 1;        // 0..1 : M group (64 rows)
    const int wn   = wid >> 1;       // 0..3 : N group (32 cols)
    const int g    = lane >> 2;      // 0..7
    const int cq   = lane & 3;       // 0..3

    if (tid < BM) {
        const int r = row0 + tid;
        if (r < n) { stok[tid] = g_tok[e][r]; swt[tid] = g_wt[e][r]; }
        else       { stok[tid] = -1;          swt[tid] = 0.0f; }
    }
    __syncthreads();

    // A-load mapping: 128 rows x 8 float4; 2 threads/row, 4 float4 each
    const int ar = tid >> 1;             // row 0..127
    const int aj = (tid & 1) * 16;       // float offset within 32-wide k chunk
    const int atok = stok[ar];
    const float* xrow = x + (size_t)(atok < 0 ? 0 : atok) * DDIM;

    // B-load mapping: 32 k-rows x 32 float4; 8 threads/row, 4 float4 each
    const int bk = tid >> 3;             // k row 0..31
    const int bq = tid & 7;              // float4 group base
    const float* We = eW + (size_t)e * DDIM * DDIM;

    float c[4][4][4];                    // [mtile][ntile][frag]
#pragma unroll
    for (int mt = 0; mt < 4; mt++)
#pragma unroll
        for (int nt = 0; nt < 4; nt++)
#pragma unroll
            for (int i = 0; i < 4; i++) c[mt][nt][i] = 0.0f;

    for (int k0 = 0; k0 < DDIM; k0 += BK) {
        // -- global prefetch into registers --
        float4 aR[4], bR[4];
#pragma unroll
        for (int i = 0; i < 4; i++)
            aR[i] = *reinterpret_cast<const float4*>(xrow + k0 + aj + i * 4);
        const float* brow = We + (size_t)(k0 + bk) * DDIM + col0;
#pragma unroll
        for (int s = 0; s < 4; s++)
            bR[s] = *reinterpret_cast<const float4*>(brow + (bq + s * 8) * 4);

        __syncthreads();   // previous tile fully consumed

        // -- cvt to tf32 and store --
#pragma unroll
        for (int i = 0; i < 4; i++) {
            uint4 u;
            u.x = f2tf32(aR[i].x); u.y = f2tf32(aR[i].y);
            u.z = f2tf32(aR[i].z); u.w = f2tf32(aR[i].w);
            *reinterpret_cast<uint4*>(&As[ar][aj + i * 4]) = u;
        }
#pragma unroll
        for (int s = 0; s < 4; s++) {
            uint4 u;
            u.x = f2tf32(bR[s].x); u.y = f2tf32(bR[s].y);
            u.z = f2tf32(bR[s].z); u.w = f2tf32(bR[s].w);
            *reinterpret_cast<uint4*>(&Bs[bk][(bq + s * 8) * 4]) = u;
        }

        __syncthreads();

        // -- compute: 4 k-substeps of 8 --
#pragma unroll
        for (int kb = 0; kb < 4; kb++) {
            const int kk = kb * 8;
            uint32_t af[4][4];           // [mtile][frag]
#pragma unroll
            for (int mt = 0; mt < 4; mt++) {
                const int m = wm * 64 + mt * 16 + g;
                af[mt][0] = As[m    ][kk + cq];
                af[mt][1] = As[m + 8][kk + cq];
                af[mt][2] = As[m    ][kk + cq + 4];
                af[mt][3] = As[m + 8][kk + cq + 4];
            }
            uint32_t bf[4][2];           // [ntile][frag]
#pragma unroll
            for (int nt = 0; nt < 4; nt++) {
                const int nn = wn * 32 + nt * 8 + g;
                bf[nt][0] = Bs[kk + cq    ][nn];
                bf[nt][1] = Bs[kk + cq + 4][nn];
            }
#pragma unroll
            for (int mt = 0; mt < 4; mt++)
#pragma unroll
                for (int nt = 0; nt < 4; nt++)
                    mma_tf32(c[mt][nt][0], c[mt][nt][1], c[mt][nt][2], c[mt][nt][3],
                             af[mt][0], af[mt][1], af[mt][2], af[mt][3],
                             bf[nt][0], bf[nt][1]);
        }
    }

    // -- epilogue: scale by routing weight, atomic-accumulate --
#pragma unroll
    for (int mt = 0; mt < 4; mt++) {
        const int lr0 = wm * 64 + mt * 16 + g;   // local rows lr0, lr0+8
#pragma unroll
        for (int half = 0; half < 2; half++) {
            const int lr  = lr0 + half * 8;
            const int tok = stok[lr];
            if (tok < 0) continue;
            const float w = swt[lr];
            float* obase = out + (size_t)tok * DDIM + col0 + wn * 32 + cq * 2;
#pragma unroll
            for (int nt = 0; nt < 4; nt++) {
                const float v0 = w * c[mt][nt][half * 2 + 0];
                const float v1 = w * c[mt][nt][half * 2 + 1];
                atomicAdd(obase + nt * 8 + 0, v0);
                atomicAdd(obase + nt * 8 + 1, v1);
            }
        }
    }
}

// ---------------------------------------------------------------------------
extern "C" void kernel_launch(void* const* d_in, const int* in_sizes, int n_in,
                              void* d_out, int out_size)
{
    const float* x  = (const float*)d_in[0];   // [4,2048,1024]
    const float* gW = (const float*)d_in[1];   // [1024,8]
    const float* gb = (const float*)d_in[2];   // [8]
    const float* eW = (const float*)d_in[3];   // [8,1024,1024]
    const float* eb = (const float*)d_in[4];   // [8,1024]
    float* out = (float*)d_out;                // [4,2048,1024]

    zero_counts_kernel<<<1, 32>>>();
    gating_kernel<<<NTOK / 8, 256>>>(x, gW, gb);
    bias_init_kernel<<<(NTOK * DDIM) / 256, 256>>>(eb, out);
    dim3 grid(DDIM / BN, NTOK / BM, NEXP);     // (8, 64, 8); most y-tiles exit early
    expert_gemm_kernel<<<grid, 256>>>(x, eW, out);
}